// round 17
// baseline (speedup 1.0000x reference)
#include <cuda_runtime.h>
#include <cuda_fp16.h>
#include <cstdint>
#include <mma.h>

using namespace nvcuda;

#define T_      8
#define H_      64
#define W_      64
#define C_      256
#define HEADS_  8
#define WS_     7
#define NPIX    (T_ * H_ * W_)          // 32768
#define M_      NPIX
#define N_      512
#define K_      256
#define NS_     (3 * WS_ * WS_)         // 147
#define SCALE_  0.17677669529663687f    // 32^-0.5
#define FBASE_  ((size_t)HEADS_ * T_ * 4096 * NS_)   // 38,535,168

// fp16 inputs + projected q (pre-scaled) / k
__device__ __align__(16) __half g_xh[(size_t)NPIX * 256];
__device__ __align__(16) __half g_wh[(size_t)512 * 256];
__device__ __align__(16) __half g_qh[(size_t)NPIX * 256];
__device__ __align__(16) __half g_kh[(size_t)NPIX * 256];

__device__ __forceinline__ void cvt8(const float4 u, const float4 v, uint4& o)
{
    __half2 p0 = __floats2half2_rn(u.x, u.y);
    __half2 p1 = __floats2half2_rn(u.z, u.w);
    __half2 p2 = __floats2half2_rn(v.x, v.y);
    __half2 p3 = __floats2half2_rn(v.z, v.w);
    o.x = *(unsigned*)&p0; o.y = *(unsigned*)&p1;
    o.z = *(unsigned*)&p2; o.w = *(unsigned*)&p3;
}

__device__ __forceinline__ int reflect_idx(int idx, int L)
{
    const int period = 2 * (L - 1);
    int m = idx % period;
    if (m < 0) m += period;
    return (m > L - 1) ? (period - m) : m;
}

// ---------------------------------------------------------------------------
// convert x and W_qk to fp16 (one kernel)
// ---------------------------------------------------------------------------
#define XN_ (NPIX * 256)          // 8388608
#define WN_ (512 * 256)           // 131072

__global__ void __launch_bounds__(256) cvt_kernel(
    const float* __restrict__ x, const float* __restrict__ wqk)
{
    const int idx = blockIdx.x * 256 + threadIdx.x;
    const long base = (long)idx * 8;
    const float* src;
    __half* dst;
    if (base < XN_) { src = x + base;           dst = g_xh + base; }
    else            { src = wqk + (base - XN_); dst = g_wh + (base - XN_); }
    uint4 o;
    cvt8(*(const float4*)src, *(const float4*)(src + 4), o);
    *(uint4*)dst = o;
}

// ---------------------------------------------------------------------------
// GEMM (128x64, cp.async double-buffered) + fused flows_k writer.
// flows_k depends only on `flows`; its 462MB of DRAM stores overlap the
// tensor/sync-bound GEMM instead of competing with attn's saturated l1tex.
// ---------------------------------------------------------------------------
#define GPITCH 72
#define ABUF_H (128 * GPITCH)       // 9216 halfs
#define BBUF_H (64 * GPITCH)        // 4608 halfs
#define GSM_TOTAL ((ABUF_H + BBUF_H) * 2 * 2)   // 55296 bytes

__device__ __forceinline__ void cp16(void* smem_dst, const void* gmem_src)
{
    uint32_t d = (uint32_t)__cvta_generic_to_shared(smem_dst);
    asm volatile("cp.async.cg.shared.global [%0], [%1], 16;\n"
                 :: "r"(d), "l"(gmem_src) : "memory");
}

__global__ void __launch_bounds__(256) gemm_qk_kernel(
    const float* __restrict__ flows, float* __restrict__ out)
{
    extern __shared__ __align__(16) char sm[];
    __half* bufh = (__half*)sm;
    __half* As[2] = { bufh,          bufh + ABUF_H + BBUF_H };
    __half* Bs[2] = { bufh + ABUF_H, bufh + 2 * ABUF_H + BBUF_H };

    const int m0   = blockIdx.x * 128;
    const int n0   = blockIdx.y * 64;
    const int tid  = threadIdx.x;
    const int wid  = tid >> 5;
    const int lane = tid & 31;
    const int wm   = wid & 3;
    const int wn   = wid >> 2;

    auto stage = [&](int kt, int b) {
        #pragma unroll
        for (int i = 0; i < 4; i++) {
            const int e   = i * 256 + tid;
            const int row = e >> 3;
            const int c8  = (e & 7) * 8;
            cp16(As[b] + row * GPITCH + c8,
                 g_xh + (size_t)(m0 + row) * 256 + kt + c8);
        }
        #pragma unroll
        for (int i = 0; i < 2; i++) {
            const int e   = i * 256 + tid;
            const int row = e >> 3;
            const int c8  = (e & 7) * 8;
            cp16(Bs[b] + row * GPITCH + c8,
                 g_wh + (size_t)(n0 + row) * 256 + kt + c8);
        }
        asm volatile("cp.async.commit_group;\n" ::: "memory");
    };

    wmma::fragment<wmma::accumulator, 16, 16, 16, float> acc[2][2];
    #pragma unroll
    for (int i = 0; i < 2; i++)
        #pragma unroll
        for (int j = 0; j < 2; j++)
            wmma::fill_fragment(acc[i][j], 0.0f);

    stage(0, 0);

    #pragma unroll
    for (int c = 0; c < 4; c++) {
        const int b = c & 1;
        if (c < 3) stage((c + 1) * 64, b ^ 1);
        if (c < 3) asm volatile("cp.async.wait_group 1;\n" ::: "memory");
        else       asm volatile("cp.async.wait_group 0;\n" ::: "memory");
        __syncthreads();

        #pragma unroll
        for (int kk = 0; kk < 64; kk += 16) {
            wmma::fragment<wmma::matrix_a, 16, 16, 16, __half, wmma::row_major> af0, af1;
            wmma::fragment<wmma::matrix_b, 16, 16, 16, __half, wmma::col_major> bf0, bf1;
            wmma::load_matrix_sync(af0, As[b] + (wm * 32)      * GPITCH + kk, GPITCH);
            wmma::load_matrix_sync(af1, As[b] + (wm * 32 + 16) * GPITCH + kk, GPITCH);
            wmma::load_matrix_sync(bf0, Bs[b] + (wn * 32)      * GPITCH + kk, GPITCH);
            wmma::load_matrix_sync(bf1, Bs[b] + (wn * 32 + 16) * GPITCH + kk, GPITCH);
            wmma::mma_sync(acc[0][0], af0, bf0, acc[0][0]);
            wmma::mma_sync(acc[0][1], af0, bf1, acc[0][1]);
            wmma::mma_sync(acc[1][0], af1, bf0, acc[1][0]);
            wmma::mma_sync(acc[1][1], af1, bf1, acc[1][1]);
        }
        __syncthreads();
    }

    // ---- epilogue: restage via smem (aliases buffers), fp16 out ----
    float* wbuf = (float*)sm + wid * 1152;   // 32 rows x pitch 36
    wmma::store_matrix_sync(wbuf,                acc[0][0], 36, wmma::mem_row_major);
    wmma::store_matrix_sync(wbuf + 16,           acc[0][1], 36, wmma::mem_row_major);
    wmma::store_matrix_sync(wbuf + 16 * 36,      acc[1][0], 36, wmma::mem_row_major);
    wmma::store_matrix_sync(wbuf + 16 * 36 + 16, acc[1][1], 36, wmma::mem_row_major);
    __syncwarp();

    {
        const float sc = (n0 < 256) ? SCALE_ : 1.0f;
        const float* src = wbuf + lane * 36;
        uint4 o[4];
        #pragma unroll
        for (int g = 0; g < 4; g++) {
            float4 u = *(const float4*)(src + g * 8);
            float4 v = *(const float4*)(src + g * 8 + 4);
            u.x *= sc; u.y *= sc; u.z *= sc; u.w *= sc;
            v.x *= sc; v.y *= sc; v.z *= sc; v.w *= sc;
            cvt8(u, v, o[g]);
        }
        const int gr = m0 + wm * 32 + lane;
        const int gc = n0 + wn * 32;
        __half* dst = (n0 < 256) ? (g_qh + (size_t)gr * 256 + gc)
                                 : (g_kh + (size_t)gr * 256 + (gc - 256));
        *(uint4*)(dst)      = o[0];
        *(uint4*)(dst + 8)  = o[1];
        *(uint4*)(dst + 16) = o[2];
        *(uint4*)(dst + 24) = o[3];
    }

    // ---- fused flows_k writer: 16 pixels per block, 2 per warp ----
    const int pixbase = (blockIdx.y * gridDim.x + blockIdx.x) * 16 + wid * 2;
    #pragma unroll
    for (int pi = 0; pi < 2; pi++) {
        const int pix = pixbase + pi;
        const int t   = pix >> 12;
        const int hw  = pix & 4095;
        const int hp  = hw >> 6;
        const int wp  = hw & 63;
        const int tp1 = (t + 1 < T_) ? t + 1 : t - 2;
        const int tp2 = (t - 1 >= 0) ? t - 1 : t + 2;
        const int di1 = (int)rintf(flows[(size_t)((t * 2 + 0) * 2 + 0) * 4096 + hw]);
        const int dj1 = (int)rintf(flows[(size_t)((t * 2 + 0) * 2 + 1) * 4096 + hw]);
        const int di2 = (int)rintf(flows[(size_t)((t * 2 + 1) * 2 + 0) * 4096 + hw]);
        const int dj2 = (int)rintf(flows[(size_t)((t * 2 + 1) * 2 + 1) * 4096 + hw]);

        for (int s = lane; s < NS_; s += 32) {
            const int slot = (s >= 49) + (s >= 98);
            const int r = s - slot * 49;
            const int a = r / 7;
            const int b = r - a * 7;
            int di = 0, dj = 0, tp = t;
            if (slot == 1) { tp = tp1; di = di1; dj = dj1; }
            if (slot == 2) { tp = tp2; di = di2; dj = dj2; }
            const int li = reflect_idx(hp + di + a - 3, H_);
            const int lj = reflect_idx(wp + dj + b - 3, W_);
            const float f0 = (float)(tp - t);
            const float f1 = (float)(li - hp);
            const float f2 = (float)(lj - wp);
            #pragma unroll
            for (int hd = 0; hd < HEADS_; hd++) {
                float* dst = out + FBASE_
                    + (size_t)((hd * T_ + t) * 4096 + hw) * (NS_ * 3) + s * 3;
                dst[0] = f0;
                dst[1] = f1;
                dst[2] = f2;
            }
        }
    }
}

// ---------------------------------------------------------------------------
// Attention: 2x2 tile; phase 1 slot-0 union rows, phase 2 slots 1/2.
// flows_k work removed (now in gemm) -> ~30% fewer l1tex wavefronts.
// ---------------------------------------------------------------------------
__device__ __forceinline__ float dot8(const uint4& kv, const __half2 q0,
                                      const __half2 q1, const __half2 q2,
                                      const __half2 q3)
{
    __half2 a = __hmul2(*(const __half2*)&kv.x, q0);
    a = __hfma2(*(const __half2*)&kv.y, q1, a);
    a = __hfma2(*(const __half2*)&kv.z, q2, a);
    a = __hfma2(*(const __half2*)&kv.w, q3, a);
    return __half2float(__hadd(__low2half(a), __high2half(a)));
}

__global__ void __launch_bounds__(256) attn_kernel(
    const float* __restrict__ flows, float* __restrict__ out)
{
    const int bid = blockIdx.x;          // 8192 tiles
    const int t   = bid >> 10;
    const int th  = (bid >> 5) & 31;
    const int tw  = bid & 31;
    const int h0  = th * 2;
    const int w0  = tw * 2;

    __shared__ int   off_s[4][NS_ + 8];
    __shared__ int   roff_s[64];
    __shared__ float attn_s[4][HEADS_ * NS_];
    __shared__ int   s_fl[4][4];

    const int tid  = threadIdx.x;
    const int warp = tid >> 5;
    const int lane = tid & 31;

    if (tid < 16) {
        const int p   = tid >> 2;
        const int idx = tid & 3;
        const int hwp = (h0 + (p >> 1)) * 64 + w0 + (p & 1);
        const int p_  = idx >> 1, c_ = idx & 1;
        s_fl[p][idx] = (int)rintf(flows[(size_t)((t * 2 + p_) * 2 + c_) * 4096 + hwp]);
    }
    if (tid >= 224 && tid < 256) {             // zero the prefetch pad
        const int p = (tid - 224) >> 3;
        off_s[p][NS_ + ((tid - 224) & 7)] = 0;
    }
    if (tid >= 160 && tid < 224) {             // slot-0 union rows 8x8
        const int r  = tid - 160;
        const int iu = r >> 3, iv = r & 7;
        roff_s[r] = (t << 12) + reflect_idx(h0 - 3 + iu, H_) * 64
                              + reflect_idx(w0 - 3 + iv, W_);
    }
    __syncthreads();

    // offsets for slots 1/2 only (slot 0 handled by union rows)
    for (int e = tid; e < 4 * (NS_ - 49); e += 256) {
        const int p  = e / (NS_ - 49);
        const int s  = 49 + (e - p * (NS_ - 49));
        const int hp = h0 + (p >> 1);
        const int wp = w0 + (p & 1);
        const int slot = (s >= 98) ? 2 : 1;
        const int r = s - slot * 49;
        const int a = r / 7;
        const int b = r - a * 7;
        int di, dj, tp;
        if (slot == 1) { tp = (t + 1 < T_) ? t + 1 : t - 2; di = s_fl[p][0]; dj = s_fl[p][1]; }
        else           { tp = (t - 1 >= 0) ? t - 1 : t + 2; di = s_fl[p][2]; dj = s_fl[p][3]; }
        const int li = reflect_idx(hp + di + a - 3, H_);
        const int lj = reflect_idx(wp + dj + b - 3, W_);
        off_s[p][s] = (tp << 12) + li * 64 + lj;
    }
    __syncthreads();

    const __half* kb = g_kh + lane * 8;
    const int head = lane >> 2;
    const bool wr = (lane & 3) == 0;

    // ================= phase 1: slot-0 union (64 rows, warp = iu) ==========
    {
        __half2 q4[4][4];
        #pragma unroll
        for (int p = 0; p < 4; p++) {
            const int pixp = (t << 12) + (h0 + (p >> 1)) * 64 + w0 + (p & 1);
            const uint4 v = *(const uint4*)(g_qh + (size_t)pixp * 256 + lane * 8);
            q4[p][0] = *(const __half2*)&v.x;
            q4[p][1] = *(const __half2*)&v.y;
            q4[p][2] = *(const __half2*)&v.z;
            q4[p][3] = *(const __half2*)&v.w;
        }

        const int iu = warp;
        uint4 kv = *(const uint4*)(kb + ((size_t)roff_s[iu * 8] << 8));
        #pragma unroll
        for (int iv = 0; iv < 8; iv++) {
            const int nxt = (iv < 7) ? iv + 1 : 7;
            uint4 nv = *(const uint4*)(kb + ((size_t)roff_s[iu * 8 + nxt] << 8));

            float v0 = dot8(kv, q4[0][0], q4[0][1], q4[0][2], q4[0][3]);
            float v1 = dot8(kv, q4[1][0], q4[1][1], q4[1][2], q4[1][3]);
            float v2 = dot8(kv, q4[2][0], q4[2][1], q4[2][2], q4[2][3]);
            float v3 = dot8(kv, q4[3][0], q4[3][1], q4[3][2], q4[3][3]);
            v0 += __shfl_xor_sync(0xffffffffu, v0, 1);
            v1 += __shfl_xor_sync(0xffffffffu, v1, 1);
            v2 += __shfl_xor_sync(0xffffffffu, v2, 1);
            v3 += __shfl_xor_sync(0xffffffffu, v3, 1);
            v0 += __shfl_xor_sync(0xffffffffu, v0, 2);
            v1 += __shfl_xor_sync(0xffffffffu, v1, 2);
            v2 += __shfl_xor_sync(0xffffffffu, v2, 2);
            v3 += __shfl_xor_sync(0xffffffffu, v3, 2);
            if (wr) {
                if (iu < 7  && iv < 7)  attn_s[0][head * NS_ + iu * 7 + iv]           = v0;
                if (iu < 7  && iv >= 1) attn_s[1][head * NS_ + iu * 7 + iv - 1]       = v1;
                if (iu >= 1 && iv < 7)  attn_s[2][head * NS_ + (iu - 1) * 7 + iv]     = v2;
                if (iu >= 1 && iv >= 1) attn_s[3][head * NS_ + (iu - 1) * 7 + iv - 1] = v3;
            }
            kv = nv;
        }
    }

    // ================= phase 2: slots 1/2 (keys 49..146), warp owns 2 pixels
    {
        const int p0    = (warp >> 2) * 2;
        const int sbase = 49 + (warp & 3);

        __half2 q[2][4];
        #pragma unroll
        for (int i = 0; i < 2; i++) {
            const int p = p0 + i;
            const int pixp = (t << 12) + (h0 + (p >> 1)) * 64 + w0 + (p & 1);
            const uint4 v = *(const uint4*)(g_qh + (size_t)pixp * 256 + lane * 8);
            q[i][0] = *(const __half2*)&v.x;
            q[i][1] = *(const __half2*)&v.y;
            q[i][2] = *(const __half2*)&v.z;
            q[i][3] = *(const __half2*)&v.w;
        }

        uint4 kv[2];
        kv[0] = *(const uint4*)(kb + ((size_t)off_s[p0][sbase]     << 8));
        kv[1] = *(const uint4*)(kb + ((size_t)off_s[p0 + 1][sbase] << 8));

        for (int s = sbase; s < NS_; s += 4) {
            const int sn = (s + 4 < NS_) ? s + 4 : NS_;
            uint4 nv0 = *(const uint4*)(kb + ((size_t)off_s[p0][sn]     << 8));
            uint4 nv1 = *(const uint4*)(kb + ((size_t)off_s[p0 + 1][sn] << 8));

            float v0 = dot8(kv[0], q[0][0], q[0][1], q[0][2], q[0][3]);
            float v1 = dot8(kv[1], q[1][0], q[1][1], q[1][2], q[1][3]);
            v0 += __shfl_xor_sync(0xffffffffu, v0, 1);
            v1 += __shfl_xor_sync(0xffffffffu, v1, 1);
            v0 += __shfl_xor_sync(0xffffffffu, v0, 2);
            v1 += __shfl_xor_sync(0xffffffffu, v1, 2);
            if (wr) {
                attn_s[p0][head * NS_ + s]     = v0;
                attn_s[p0 + 1][head * NS_ + s] = v1;
            }
            kv[0] = nv0;
            kv[1] = nv1;
        }
    }
    __syncthreads();

    // attn stores: (1, HEADS, T, H, W, 147)
    #pragma unroll
    for (int p = 0; p < 4; p++) {
        const int hwp = (h0 + (p >> 1)) * 64 + w0 + (p & 1);
        #pragma unroll
        for (int hd = 0; hd < HEADS_; hd++) {
            if (tid < NS_)
                out[(size_t)((hd * T_ + t) * 4096 + hwp) * NS_ + tid] =
                    attn_s[p][hd * NS_ + tid];
        }
    }
}

// ---------------------------------------------------------------------------
extern "C" void kernel_launch(void* const* d_in, const int* in_sizes, int n_in,
                              void* d_out, int out_size)
{
    const float* x     = (const float*)d_in[0];   // (8,64,64,256)
    const float* flows = (const float*)d_in[1];   // (1,8,2,2,64,64)
    const float* wqk   = (const float*)d_in[2];   // (512,256)
    float* out = (float*)d_out;

    cudaFuncSetAttribute(gemm_qk_kernel,
                         cudaFuncAttributeMaxDynamicSharedMemorySize, GSM_TOTAL);

    cvt_kernel<<<(XN_ + WN_) / 8 / 256, 256>>>(x, wqk);
    dim3 gg(M_ / 128, N_ / 64);
    gemm_qk_kernel<<<gg, 256, GSM_TOTAL>>>(flows, out);
    attn_kernel<<<NPIX / 4, 256>>>(flows, out);
}